// round 8
// baseline (speedup 1.0000x reference)
#include <cuda_runtime.h>
#include <cuda_bf16.h>
#include <math.h>
#include <cstdint>

#define BB 64
#define CINN 64
#define COUTT 128
#define NPIX 1024
#define TC 4

// Per-CTA SMEM: Ys 36 c-rows x 20 rows x 32 px fp32 = 92160 B; W 40x272 = 10880; red 128.
#define YSTR 640
#define SM_W   92160
#define SM_RED 103040
#define SMEM_TOTAL 103296

// A_g: per (b,chunk=16cin) plane of 4096 uint4 in m16n8k8-tf32 fragment order:
// idx = mtile*64 + kk*32 + lane; uint4 = {a0,a1,a2,a3} for px rows mtile*16..+15, k=chunk*16+kk*8..+7
__device__ uint4 A_g[BB * 4 * 4096];
__device__ float g_psum[COUTT * BB * 2];
__device__ float g_psumsq[COUTT * BB * 2];
__device__ float g_scale[COUTT];
__device__ float g_shift[COUTT];

__device__ __forceinline__ void mma_tf32(float* d, const uint32_t* a, const uint32_t* b) {
    asm volatile("mma.sync.aligned.m16n8k8.row.col.f32.tf32.tf32.f32 "
        "{%0,%1,%2,%3}, {%4,%5,%6,%7}, {%8,%9}, {%0,%1,%2,%3};"
        : "+f"(d[0]), "+f"(d[1]), "+f"(d[2]), "+f"(d[3])
        : "r"(a[0]), "r"(a[1]), "r"(a[2]), "r"(a[3]), "r"(b[0]), "r"(b[1]));
}
__device__ __forceinline__ uint32_t to_tf32(float f) {
    uint32_t o;
    asm("cvt.rna.tf32.f32 %0, %1;" : "=r"(o) : "f"(f));
    return o;
}
__device__ __forceinline__ int fd3(int a) { return (a + 24) / 3 - 8; }  // floor(a/3), a>=-24

// ---- prologue: per (chunk,b) emit tf32 A plane in fragment order (unchanged, verified) ----
__global__ void __launch_bounds__(512) build_A(const float* __restrict__ x)
{
    extern __shared__ float Xs[];   // [16][1032]
    const int tid = threadIdx.x, chunk = blockIdx.x, b = blockIdx.y;
    const float4* xg = (const float4*)(x + (size_t)b * CINN * NPIX + chunk * 16 * NPIX);
#pragma unroll
    for (int j = 0; j < 8; j++) {
        int idx = tid + 512 * j;
        int ci = idx >> 8, px4 = idx & 255;
        *(float4*)(Xs + ci * 1032 + px4 * 4) = xg[idx];
    }
    __syncthreads();
    uint4* pb = A_g + (size_t)(b * 4 + chunk) * 4096;
#pragma unroll
    for (int j = 0; j < 8; j++) {
        int idx = tid + 512 * j;
        int l = idx & 31, t = l & 3, g = l >> 2;
        int kk = (idx >> 5) & 1, mtile = idx >> 6;
        int px = mtile * 16 + g, k = kk * 8 + t;
        uint4 v;
        v.x = to_tf32(Xs[k * 1032 + px]);
        v.y = to_tf32(Xs[k * 1032 + px + 8]);
        v.z = to_tf32(Xs[(k + 4) * 1032 + px]);
        v.w = to_tf32(Xs[(k + 4) * 1032 + px + 8]);
        pb[idx] = v;
    }
}

__global__ void __launch_bounds__(256, 2)
fused_kernel(const int* __restrict__ hh, const int* __restrict__ wwp,
             const float* __restrict__ weight, const float* __restrict__ bias,
             float* __restrict__ out)
{
    extern __shared__ char smem[];
    float* Ys = (float*)smem;
    const int tid = threadIdx.x, wid = tid >> 5, l = tid & 31;
    const int half = blockIdx.x;
    const int co0 = blockIdx.y * TC;
    const int b = blockIdx.z;

    // zero + fill W (tf32, row n = tap*4+c, 272B stride; rows 36..39 stay 0)
    for (int i = tid; i < 2720; i += 256) *(uint32_t*)(smem + SM_W + 4 * i) = 0u;
    __syncthreads();
    for (int i = tid; i < TC * CINN * 9; i += 256) {
        int c = i / 576, r = i - c * 576, ci = r / 9, tap = r - ci * 9;
        float w = weight[(co0 + c) * 576 + ci * 9 + tap];
        *(uint32_t*)(smem + SM_W + (tap * 4 + c) * 272 + ci * 4) = to_tf32(w);
    }
    __syncthreads();

    // GEMM over 20-row window: mtiles mt0..mt0+39, 5 per warp
    const int mt0 = 24 * half;          // window covers px rows 12*half*32 .. +639
    float acc[5][5][4];
#pragma unroll
    for (int mt = 0; mt < 5; mt++)
#pragma unroll
        for (int nt = 0; nt < 5; nt++)
#pragma unroll
            for (int k = 0; k < 4; k++) acc[mt][nt][k] = 0.f;

    const int lq = l & 3, ln = l >> 2;

#pragma unroll 1
    for (int ch = 0; ch < 4; ch++) {
        const uint4* pb = A_g + (size_t)(b * 4 + ch) * 4096;
#pragma unroll
        for (int kk = 0; kk < 2; kk++) {
            uint32_t bf[5][2];
#pragma unroll
            for (int nt = 0; nt < 5; nt++) {
                int base = SM_W + (nt * 8 + ln) * 272 + (ch * 16 + kk * 8 + lq) * 4;
                bf[nt][0] = *(uint32_t*)(smem + base);
                bf[nt][1] = *(uint32_t*)(smem + base + 16);
            }
#pragma unroll
            for (int mt = 0; mt < 5; mt++) {
                uint4 a = pb[(mt0 + wid * 5 + mt) * 64 + kk * 32 + l];
#pragma unroll
                for (int nt = 0; nt < 5; nt++) mma_tf32(acc[mt][nt], (const uint32_t*)&a, bf[nt]);
            }
        }
    }
    __syncthreads();   // W reads done before any Ys write? (W region disjoint from Ys; sync for phase order)

    // readout into local 20-row window: local px = global px - 384*half
#pragma unroll
    for (int mt = 0; mt < 5; mt++)
#pragma unroll
        for (int nt = 0; nt < 5; nt++) {
            int c0 = nt * 8 + 2 * lq;
            if (nt == 4 && lq >= 2) continue;  // cols 36..39 unused
            int lpx = (mt0 + wid * 5 + mt) * 16 + ln - 384 * half;
            Ys[c0 * YSTR + lpx]           = acc[mt][nt][0];
            Ys[(c0 + 1) * YSTR + lpx]     = acc[mt][nt][1];
            Ys[c0 * YSTR + lpx + 8]       = acc[mt][nt][2];
            Ys[(c0 + 1) * YSTR + lpx + 8] = acc[mt][nt][3];
        }
    __syncthreads();

    // ---- combine (row/col dedup + center-row specialization) ----
    int dh = 96 / hh[b];  if (dh < 1) dh = 1;
    int dw = 96 / wwp[b]; if (dw < 1) dw = 1;
    int rv[3][2]; bool rsel[3][3];
    int dcl[3], dch[3]; bool cdup[3], csel[3][3];
#pragma unroll
    for (int k = 0; k < 3; k++) {
        int d0 = fd3((k - 1) * dh), d1 = fd3(1 + (k - 1) * dh), d2 = fd3(2 + (k - 1) * dh);
        rv[k][0] = d0; rv[k][1] = d2;
        rsel[k][0] = false; rsel[k][1] = (d1 != d0); rsel[k][2] = (d2 != d0);
        int c0 = fd3((k - 1) * dw), c1 = fd3(1 + (k - 1) * dw), c2 = fd3(2 + (k - 1) * dw);
        dcl[k] = c0; dch[k] = c2; cdup[k] = (c2 != c0);
        csel[k][0] = false; csel[k][1] = (c1 != c0); csel[k][2] = (c2 != c0);
    }
    const bool vneed0 = (rv[0][1] != rv[0][0]);
    const bool vneed2 = (rv[2][1] != rv[2][0]);
    float* red = (float*)(smem + SM_RED);
    const int rbias = 12 * half;

#pragma unroll 1
    for (int co = 0; co < TC; co++) {
        const float bias_v = bias[co0 + co];
        float lsum = 0.f, lsq = 0.f;
#pragma unroll
        for (int jj = 0; jj < 2; jj++) {
            int pixl = tid + 256 * jj;
            int pyl = pixl >> 5, px = pixl & 31;
            int grow = half * 16 + pyl;

            // center row (ki=1): row offset always 0, row always valid
            float RS1[3];
            {
                int rb = (grow - rbias) * 32;
                float L0[3], L1[3];
#pragma unroll
                for (int kj = 0; kj < 3; kj++) {
                    const float* P = &Ys[((3 + kj) * TC + co) * YSTR + rb];
                    int cA = px + dcl[kj];
                    L0[kj] = ((unsigned)cA < 32u) ? P[cA] : 0.f;
                    if (cdup[kj]) {
                        int cB = px + dch[kj];
                        L1[kj] = ((unsigned)cB < 32u) ? P[cB] : 0.f;
                    } else L1[kj] = L0[kj];
                }
#pragma unroll
                for (int s = 0; s < 3; s++)
                    RS1[s] = L0[1] + (csel[0][s] ? L1[0] : L0[0])
                                   + (csel[2][s] ? L1[2] : L0[2]);
            }
            // side rows (ki=0,2), v=1 guarded by uniform vneed
            float RS0[2][3], RS2[2][3];
#pragma unroll
            for (int ki = 0; ki < 3; ki += 2) {
                float (*RS)[3] = (ki == 0) ? RS0 : RS2;
                const bool vneed = (ki == 0) ? vneed0 : vneed2;
                const int nv = vneed ? 2 : 1;
#pragma unroll
                for (int v = 0; v < 2; v++) {
                    if (v >= nv) break;
                    int row = grow + rv[ki][v];
                    bool rok = (unsigned)row < 32u;
                    int rb = (row - rbias) * 32;
                    float L0[3], L1[3];
#pragma unroll
                    for (int kj = 0; kj < 3; kj++) {
                        const float* P = &Ys[((ki * 3 + kj) * TC + co) * YSTR + rb];
                        int cA = px + dcl[kj];
                        L0[kj] = (rok && (unsigned)cA < 32u) ? P[cA] : 0.f;
                        if (cdup[kj]) {
                            int cB = px + dch[kj];
                            L1[kj] = (rok && (unsigned)cB < 32u) ? P[cB] : 0.f;
                        } else L1[kj] = L0[kj];
                    }
#pragma unroll
                    for (int s = 0; s < 3; s++)
                        RS[v][s] = L0[1] + (csel[0][s] ? L1[0] : L0[0])
                                         + (csel[2][s] ? L1[2] : L0[2]);
                }
                if (!vneed) {
#pragma unroll
                    for (int s = 0; s < 3; s++) RS[1][s] = RS[0][s];
                }
            }
            float mx = -INFINITY;
#pragma unroll
            for (int r = 0; r < 3; r++)
#pragma unroll
                for (int s = 0; s < 3; s++) {
                    float v0 = rsel[0][r] ? RS0[1][s] : RS0[0][s];
                    float v2 = rsel[2][r] ? RS2[1][s] : RS2[0][s];
                    mx = fmaxf(mx, bias_v + v0 + RS1[s] + v2);
                }
            out[((size_t)(b * COUTT + co0 + co) << 10) + half * 512 + pixl] = mx;
            lsum += mx; lsq += mx * mx;
        }
#pragma unroll
        for (int o = 16; o > 0; o >>= 1) {
            lsum += __shfl_xor_sync(0xFFFFFFFFu, lsum, o);
            lsq  += __shfl_xor_sync(0xFFFFFFFFu, lsq,  o);
        }
        if (l == 0) { red[(co * 8 + wid) * 2] = lsum; red[(co * 8 + wid) * 2 + 1] = lsq; }
    }
    __syncthreads();
    if (tid < TC) {
        float s = 0.f, q = 0.f;
#pragma unroll
        for (int wdx = 0; wdx < 8; wdx++) {
            s += red[(tid * 8 + wdx) * 2];
            q += red[(tid * 8 + wdx) * 2 + 1];
        }
        g_psum  [(co0 + tid) * (BB * 2) + b * 2 + half] = s;
        g_psumsq[(co0 + tid) * (BB * 2) + b * 2 + half] = q;
    }
}

// warp per channel: 128 partials each
__global__ void __launch_bounds__(1024)
stats_kernel(const float* __restrict__ gamma, const float* __restrict__ beta)
{
    int gw = (blockIdx.x * 1024 + threadIdx.x) >> 5;   // channel 0..127
    int l = threadIdx.x & 31;
    float s = 0.f, q = 0.f;
#pragma unroll
    for (int i = 0; i < 4; i++) {
        s += g_psum  [gw * 128 + l + 32 * i];
        q += g_psumsq[gw * 128 + l + 32 * i];
    }
#pragma unroll
    for (int o = 16; o > 0; o >>= 1) {
        s += __shfl_xor_sync(0xFFFFFFFFu, s, o);
        q += __shfl_xor_sync(0xFFFFFFFFu, q, o);
    }
    if (l == 0) {
        const float inv = 1.0f / 65536.0f;
        float mean = s * inv, var = q * inv - mean * mean;
        float sc = gamma[gw] * rsqrtf(var + 1e-5f);
        g_scale[gw] = sc;
        g_shift[gw] = beta[gw] - mean * sc;
    }
}

__global__ void __launch_bounds__(1024)
apply_kernel(float* __restrict__ out)
{
    int i0 = blockIdx.x * 4096 + threadIdx.x;
#pragma unroll
    for (int j = 0; j < 4; j++) {
        int i = i0 + j * 1024;
        int c = (i >> 8) & 127;
        float4 v = ((float4*)out)[i];
        float sc = g_scale[c], sh = g_shift[c];
        v.x = fmaxf(fmaf(v.x, sc, sh), 0.f);
        v.y = fmaxf(fmaf(v.y, sc, sh), 0.f);
        v.z = fmaxf(fmaf(v.z, sc, sh), 0.f);
        v.w = fmaxf(fmaf(v.w, sc, sh), 0.f);
        ((float4*)out)[i] = v;
    }
}

extern "C" void kernel_launch(void* const* d_in, const int* in_sizes, int n_in,
                              void* d_out, int out_size)
{
    const float* x      = (const float*)d_in[0];
    const int*   h      = (const int*)  d_in[1];
    const int*   w      = (const int*)  d_in[2];
    const float* weight = (const float*)d_in[3];
    const float* bias   = (const float*)d_in[4];
    const float* gamma  = (const float*)d_in[5];
    const float* beta   = (const float*)d_in[6];
    float* out = (float*)d_out;

    cudaFuncSetAttribute(build_A, cudaFuncAttributeMaxDynamicSharedMemorySize, 66048);
    cudaFuncSetAttribute(fused_kernel, cudaFuncAttributeMaxDynamicSharedMemorySize, SMEM_TOTAL);

    build_A<<<dim3(4, BB), 512, 66048>>>(x);
    fused_kernel<<<dim3(2, COUTT / TC, BB), 256, SMEM_TOTAL>>>(h, w, weight, bias, out);
    stats_kernel<<<4, 1024>>>(gamma, beta);
    apply_kernel<<<512, 1024>>>(out);
}

// round 9
// speedup vs baseline: 1.2935x; 1.2935x over previous
#include <cuda_runtime.h>
#include <cuda_bf16.h>
#include <math.h>
#include <cstdint>

#define BB 64
#define CINN 64
#define COUTT 128
#define NPIX 1024
#define TC 4

// fused SMEM: Ys[36864 f32] = 147456 bytes; W region (40 rows x 272B) aliases Ys tail at
// 131072 (W read only during GEMM, Ys written only after GEMM sync). red at 147456.
#define SM_W  131072
#define SM_RED 147456
#define SMEM_TOTAL 147584

// A_g: per (b,chunk=16cin) plane of 4096 uint4 in m16n8k8-tf32 fragment order:
// idx = mtile*64 + kk*32 + lane; uint4 = {a0,a1,a2,a3} for px rows mtile*16..+15, k=chunk*16+kk*8..+7
__device__ uint4 A_g[BB * 4 * 4096];
__device__ float g_psum[COUTT * BB];
__device__ float g_psumsq[COUTT * BB];
__device__ float g_scale[COUTT];
__device__ float g_shift[COUTT];

__device__ __forceinline__ void mma_tf32(float* d, const uint32_t* a, const uint32_t* b) {
    asm volatile("mma.sync.aligned.m16n8k8.row.col.f32.tf32.tf32.f32 "
        "{%0,%1,%2,%3}, {%4,%5,%6,%7}, {%8,%9}, {%0,%1,%2,%3};"
        : "+f"(d[0]), "+f"(d[1]), "+f"(d[2]), "+f"(d[3])
        : "r"(a[0]), "r"(a[1]), "r"(a[2]), "r"(a[3]), "r"(b[0]), "r"(b[1]));
}
__device__ __forceinline__ uint32_t to_tf32(float f) {
    uint32_t o;
    asm("cvt.rna.tf32.f32 %0, %1;" : "=r"(o) : "f"(f));
    return o;
}
__device__ __forceinline__ int fd3(int a) { return (a + 24) / 3 - 8; }  // floor(a/3), a>=-24

// ---- prologue: per (chunk,b) emit tf32 A plane in fragment order (verified) ----
__global__ void __launch_bounds__(512) build_A(const float* __restrict__ x)
{
    extern __shared__ float Xs[];   // [16][1032]
    const int tid = threadIdx.x, chunk = blockIdx.x, b = blockIdx.y;
    const float4* xg = (const float4*)(x + (size_t)b * CINN * NPIX + chunk * 16 * NPIX);
#pragma unroll
    for (int j = 0; j < 8; j++) {
        int idx = tid + 512 * j;
        int ci = idx >> 8, px4 = idx & 255;
        *(float4*)(Xs + ci * 1032 + px4 * 4) = xg[idx];
    }
    __syncthreads();
    uint4* pb = A_g + (size_t)(b * 4 + chunk) * 4096;
#pragma unroll
    for (int j = 0; j < 8; j++) {
        int idx = tid + 512 * j;
        int l = idx & 31, t = l & 3, g = l >> 2;
        int kk = (idx >> 5) & 1, mtile = idx >> 6;
        int px = mtile * 16 + g, k = kk * 8 + t;
        uint4 v;
        v.x = to_tf32(Xs[k * 1032 + px]);
        v.y = to_tf32(Xs[k * 1032 + px + 8]);
        v.z = to_tf32(Xs[(k + 4) * 1032 + px]);
        v.w = to_tf32(Xs[(k + 4) * 1032 + px + 8]);
        pb[idx] = v;
    }
}

__global__ void __launch_bounds__(512, 1)
fused_kernel(const int* __restrict__ hh, const int* __restrict__ wwp,
             const float* __restrict__ weight, const float* __restrict__ bias,
             float* __restrict__ out)
{
    extern __shared__ char smem[];
    float* Ys = (float*)smem;
    const int tid = threadIdx.x, wid = tid >> 5, l = tid & 31;
    const int b = blockIdx.y, co0 = blockIdx.x * TC;

    // zero W region (rows 36..39 must read as 0)
    for (int i = tid; i < 2720; i += 512) *(uint32_t*)(smem + SM_W + 4 * i) = 0u;
    __syncthreads();
    // weights tf32: row n = tap*4+c, 272B stride (68 words -> conflict-free B-frag LDS)
    for (int i = tid; i < TC * CINN * 9; i += 512) {
        int c = i / 576, r = i - c * 576, ci = r / 9, tap = r - ci * 9;
        float w = weight[(co0 + c) * 576 + ci * 9 + tap];
        *(uint32_t*)(smem + SM_W + (tap * 4 + c) * 272 + ci * 4) = to_tf32(w);
    }
    __syncthreads();

    float acc[4][5][4];
#pragma unroll
    for (int mt = 0; mt < 4; mt++)
#pragma unroll
        for (int nt = 0; nt < 5; nt++)
#pragma unroll
            for (int k = 0; k < 4; k++) acc[mt][nt][k] = 0.f;

    const int lq = l & 3, ln = l >> 2;
    const int px0 = wid * 64;

#pragma unroll 1
    for (int ch = 0; ch < 4; ch++) {
        const uint4* pb = A_g + (size_t)(b * 4 + ch) * 4096;
#pragma unroll
        for (int kk = 0; kk < 2; kk++) {
            uint32_t bf[5][2];
#pragma unroll
            for (int nt = 0; nt < 5; nt++) {
                int base = SM_W + (nt * 8 + ln) * 272 + (ch * 16 + kk * 8 + lq) * 4;
                bf[nt][0] = *(uint32_t*)(smem + base);
                bf[nt][1] = *(uint32_t*)(smem + base + 16);
            }
#pragma unroll
            for (int mt = 0; mt < 4; mt++) {
                uint4 a = pb[(wid * 4 + mt) * 64 + kk * 32 + l];
#pragma unroll
                for (int nt = 0; nt < 5; nt++) mma_tf32(acc[mt][nt], (const uint32_t*)&a, bf[nt]);
            }
        }
    }
    __syncthreads();   // W reads done; Ys (aliasing W tail) may be written

    // readout: D frag m16n8: d0/d1 row ln cols 2lq,2lq+1; d2/d3 row ln+8
#pragma unroll
    for (int mt = 0; mt < 4; mt++)
#pragma unroll
        for (int nt = 0; nt < 5; nt++) {
            int c0 = nt * 8 + 2 * lq;
            if (nt == 4 && lq >= 2) continue;  // cols 36..39 unused
            int px = px0 + mt * 16 + ln;
            Ys[c0 * NPIX + px]            = acc[mt][nt][0];
            Ys[(c0 + 1) * NPIX + px]      = acc[mt][nt][1];
            Ys[c0 * NPIX + px + 8]        = acc[mt][nt][2];
            Ys[(c0 + 1) * NPIX + px + 8]  = acc[mt][nt][3];
        }
    __syncthreads();

    // ---- combine: row/col dedup + center-row specialization + uniform v-guards ----
    const int co_l = tid >> 7, lane128 = tid & 127;
    int dh = 96 / hh[b];  if (dh < 1) dh = 1;
    int dw = 96 / wwp[b]; if (dw < 1) dw = 1;
    int rv[3][2]; bool rsel[3][3];
    int dcl[3], dch[3]; bool cdup[3], csel[3][3];
#pragma unroll
    for (int k = 0; k < 3; k++) {
        int d0 = fd3((k - 1) * dh), d1 = fd3(1 + (k - 1) * dh), d2 = fd3(2 + (k - 1) * dh);
        rv[k][0] = d0; rv[k][1] = d2;
        rsel[k][0] = false; rsel[k][1] = (d1 != d0); rsel[k][2] = (d2 != d0);
        int c0 = fd3((k - 1) * dw), c1 = fd3(1 + (k - 1) * dw), c2 = fd3(2 + (k - 1) * dw);
        dcl[k] = c0; dch[k] = c2; cdup[k] = (c2 != c0);
        csel[k][0] = false; csel[k][1] = (c1 != c0); csel[k][2] = (c2 != c0);
    }
    const bool vneed0 = (rv[0][1] != rv[0][0]);
    const bool vneed2 = (rv[2][1] != rv[2][0]);
    const float bias_v = bias[co0 + co_l];
    float lsum = 0.f, lsq = 0.f;

#pragma unroll 2
    for (int j = 0; j < 8; j++) {
        int pix = lane128 + (j << 7), py = pix >> 5, px = pix & 31;

        // center row (ki=1): offset 0, always in-bounds; bias folded in
        float RS1[3];
        {
            int rb = py * 32;
            float L0[3], L1[3];
#pragma unroll
            for (int kj = 0; kj < 3; kj++) {
                const float* P = &Ys[((3 + kj) * TC + co_l) * NPIX + rb];
                int cA = px + dcl[kj];
                L0[kj] = ((unsigned)cA < 32u) ? P[cA] : 0.f;
                if (cdup[kj]) {
                    int cB = px + dch[kj];
                    L1[kj] = ((unsigned)cB < 32u) ? P[cB] : 0.f;
                } else L1[kj] = L0[kj];
            }
#pragma unroll
            for (int s = 0; s < 3; s++)
                RS1[s] = bias_v + (L0[1] + (csel[0][s] ? L1[0] : L0[0])
                                         + (csel[2][s] ? L1[2] : L0[2]));
        }
        // side rows (ki=0,2); v=1 only when offsets differ (CTA-uniform)
        float RS0[2][3], RS2[2][3];
#pragma unroll
        for (int ki = 0; ki < 3; ki += 2) {
            float (*RS)[3] = (ki == 0) ? RS0 : RS2;
            const bool vneed = (ki == 0) ? vneed0 : vneed2;
#pragma unroll
            for (int v = 0; v < 2; v++) {
                if (v == 1 && !vneed) {
#pragma unroll
                    for (int s = 0; s < 3; s++) RS[1][s] = RS[0][s];
                    break;
                }
                int row = py + rv[ki][v];
                bool rok = (unsigned)row < 32u;
                int rb = row * 32;
                float L0[3], L1[3];
#pragma unroll
                for (int kj = 0; kj < 3; kj++) {
                    const float* P = &Ys[((ki * 3 + kj) * TC + co_l) * NPIX + rb];
                    int cA = px + dcl[kj];
                    L0[kj] = (rok && (unsigned)cA < 32u) ? P[cA] : 0.f;
                    if (cdup[kj]) {
                        int cB = px + dch[kj];
                        L1[kj] = (rok && (unsigned)cB < 32u) ? P[cB] : 0.f;
                    } else L1[kj] = L0[kj];
                }
#pragma unroll
                for (int s = 0; s < 3; s++)
                    RS[v][s] = L0[1] + (csel[0][s] ? L1[0] : L0[0])
                                     + (csel[2][s] ? L1[2] : L0[2]);
            }
        }
        float mx = -INFINITY;
#pragma unroll
        for (int r = 0; r < 3; r++)
#pragma unroll
            for (int s = 0; s < 3; s++) {
                float v0 = rsel[0][r] ? RS0[1][s] : RS0[0][s];
                float v2 = rsel[2][r] ? RS2[1][s] : RS2[0][s];
                mx = fmaxf(mx, v0 + RS1[s] + v2);
            }
        out[((size_t)b * COUTT + co0 + co_l) * NPIX + pix] = mx;
        lsum += mx; lsq += mx * mx;
    }
#pragma unroll
    for (int o = 16; o > 0; o >>= 1) {
        lsum += __shfl_xor_sync(0xFFFFFFFFu, lsum, o);
        lsq  += __shfl_xor_sync(0xFFFFFFFFu, lsq,  o);
    }
    __syncthreads();
    float* red = (float*)(smem + SM_RED);
    if (l == 0) { red[wid * 2] = lsum; red[wid * 2 + 1] = lsq; }
    __syncthreads();
    if (tid < TC) {
        int c = tid;
        float s = red[8*c] + red[8*c+2] + red[8*c+4] + red[8*c+6];
        float q = red[8*c+1] + red[8*c+3] + red[8*c+5] + red[8*c+7];
        g_psum[(co0 + c) * BB + b] = s;
        g_psumsq[(co0 + c) * BB + b] = q;
    }
}

// warp-per-channel: grid 4 x 1024 threads = 128 warps
__global__ void __launch_bounds__(1024)
stats_kernel(const float* __restrict__ gamma, const float* __restrict__ beta)
{
    int gw = (blockIdx.x * 1024 + threadIdx.x) >> 5;   // channel 0..127
    int l = threadIdx.x & 31;
    float s = g_psum[gw * BB + l] + g_psum[gw * BB + 32 + l];
    float q = g_psumsq[gw * BB + l] + g_psumsq[gw * BB + 32 + l];
#pragma unroll
    for (int o = 16; o > 0; o >>= 1) {
        s += __shfl_xor_sync(0xFFFFFFFFu, s, o);
        q += __shfl_xor_sync(0xFFFFFFFFu, q, o);
    }
    if (l == 0) {
        const float inv = 1.0f / 65536.0f;
        float mean = s * inv, var = q * inv - mean * mean;
        float sc = gamma[gw] * rsqrtf(var + 1e-5f);
        g_scale[gw] = sc;
        g_shift[gw] = beta[gw] - mean * sc;
    }
}

__global__ void __launch_bounds__(1024)
apply_kernel(float* __restrict__ out)
{
    int i0 = blockIdx.x * 4096 + threadIdx.x;
#pragma unroll
    for (int j = 0; j < 4; j++) {
        int i = i0 + j * 1024;
        int c = (i >> 8) & 127;
        float4 v = ((float4*)out)[i];
        float sc = g_scale[c], sh = g_shift[c];
        v.x = fmaxf(fmaf(v.x, sc, sh), 0.f);
        v.y = fmaxf(fmaf(v.y, sc, sh), 0.f);
        v.z = fmaxf(fmaf(v.z, sc, sh), 0.f);
        v.w = fmaxf(fmaf(v.w, sc, sh), 0.f);
        ((float4*)out)[i] = v;
    }
}

extern "C" void kernel_launch(void* const* d_in, const int* in_sizes, int n_in,
                              void* d_out, int out_size)
{
    const float* x      = (const float*)d_in[0];
    const int*   h      = (const int*)  d_in[1];
    const int*   w      = (const int*)  d_in[2];
    const float* weight = (const float*)d_in[3];
    const float* bias   = (const float*)d_in[4];
    const float* gamma  = (const float*)d_in[5];
    const float* beta   = (const float*)d_in[6];
    float* out = (float*)d_out;

    cudaFuncSetAttribute(build_A, cudaFuncAttributeMaxDynamicSharedMemorySize, 66048);
    cudaFuncSetAttribute(fused_kernel, cudaFuncAttributeMaxDynamicSharedMemorySize, SMEM_TOTAL);

    build_A<<<dim3(4, BB), 512, 66048>>>(x);
    fused_kernel<<<dim3(COUTT / TC, BB), 512, SMEM_TOTAL>>>(h, w, weight, bias, out);
    stats_kernel<<<4, 1024>>>(gamma, beta);
    apply_kernel<<<512, 1024>>>(out);
}